// round 9
// baseline (speedup 1.0000x reference)
#include <cuda_runtime.h>
#include <cuda_bf16.h>
#include <math.h>
#include <stdint.h>

// Problem constants
#define Asz   384
#define Tsz   128
#define Bsz   1024
#define Lsz   50
#define G4    1536
#define BA    (Bsz*Asz)
#define OUTLD (Lsz*Asz)

// GEMM tiling
#define TM    128
#define TN    96
#define KC    128           // bf16 K elems per chunk (256B payload per row)
#define ROWB  272           // smem row stride bytes (256 payload + 16 pad)
#define NT    384           // 12 warps: 4(M) x 3(N), warp tile 32x32
#define NSTG  3
#define STAGE ((TM + TN) * ROWB)       // 60928 B
#define SMEMB (NSTG * STAGE)           // 182784 B (1 CTA/SM)
#define NSEG  ((TM + TN) * 16)         // 3584 16B copies per chunk

// ---------------------------------------------------------------------------
// Device scratch
// ---------------------------------------------------------------------------
__device__ __align__(128) __nv_bfloat16 g_Wcomb[3][G4][768]; // gate-interleaved rows: [x | h]
__device__ __align__(128) __nv_bfloat16 g_Wtag[G4][Tsz];     // gate-interleaved rows, tag slice
__device__ __align__(128) __nv_bfloat16 g_Wlb[Asz][Asz];
__device__ __align__(128) __nv_bfloat16 g_tagsb[Bsz][Tsz];
__device__ __align__(128) __nv_bfloat16 g_hb[3][2][BA];
__device__ __align__(128) __nv_bfloat16 g_prevb[2][BA];
__device__ __align__(128) float g_c[3][BA];
__device__ __align__(128) float g_tagbias[Bsz * G4];
__device__ __align__(128) float g_biasI[3][G4];

__device__ __forceinline__ float sigf(float x) { return 1.0f / (1.0f + __expf(-x)); }
__device__ __forceinline__ float tanhf_fast(float x) { return 2.0f / (1.0f + __expf(-2.0f * x)) - 1.0f; }

// ---------------------------------------------------------------------------
// PTX helpers
// ---------------------------------------------------------------------------
__device__ __forceinline__ uint32_t smem_u32(const void* p)
{
    uint32_t a;
    asm("{ .reg .u64 t; cvta.to.shared.u64 t, %1; cvt.u32.u64 %0, t; }" : "=r"(a) : "l"(p));
    return a;
}

__device__ __forceinline__ void cpa16(uint32_t s, const void* g)
{
    asm volatile("cp.async.cg.shared.global [%0], [%1], 16;" :: "r"(s), "l"(g));
}
#define CP_COMMIT()  asm volatile("cp.async.commit_group;")
template<int N>
__device__ __forceinline__ void cp_wait() { asm volatile("cp.async.wait_group %0;" :: "n"(N) : "memory"); }

__device__ __forceinline__ void ldsm_x4(uint32_t r[4], uint32_t addr)
{
    asm volatile("ldmatrix.sync.aligned.m8n8.x4.shared.b16 {%0,%1,%2,%3}, [%4];"
        : "=r"(r[0]), "=r"(r[1]), "=r"(r[2]), "=r"(r[3]) : "r"(addr));
}

__device__ __forceinline__ void mma_bf16(float c[4], const uint32_t a[4], const uint32_t b0, const uint32_t b1)
{
    asm volatile(
        "mma.sync.aligned.m16n8k16.row.col.f32.bf16.bf16.f32 "
        "{%0,%1,%2,%3},{%4,%5,%6,%7},{%8,%9},{%0,%1,%2,%3};"
        : "+f"(c[0]), "+f"(c[1]), "+f"(c[2]), "+f"(c[3])
        : "r"(a[0]), "r"(a[1]), "r"(a[2]), "r"(a[3]), "r"(b0), "r"(b1));
}

// ---------------------------------------------------------------------------
// Prep: convert/interleave weights, biases, tags; init states + out[:,0,:]
// ---------------------------------------------------------------------------
__global__ void prep_kernel(
    const float* __restrict__ tags,
    const float* __restrict__ Wih0, const float* __restrict__ Whh0,
    const float* __restrict__ bih0, const float* __restrict__ bhh0,
    const float* __restrict__ Wih1, const float* __restrict__ Whh1,
    const float* __restrict__ bih1, const float* __restrict__ bhh1,
    const float* __restrict__ Wih2, const float* __restrict__ Whh2,
    const float* __restrict__ bih2, const float* __restrict__ bhh2,
    const float* __restrict__ Wl,
    float* __restrict__ out)
{
    const int gid = blockIdx.x * blockDim.x + threadIdx.x;
    const int GT  = gridDim.x * blockDim.x;

    for (int idx = gid; idx < BA; idx += GT) {
        int m = idx / Asz, n = idx - m * Asz;
        float v = (n == 1) ? 1.0f : 0.0f;   // START = 1
        out[(size_t)m * OUTLD + n] = v;
        g_prevb[0][idx] = __float2bfloat16_rn(v);
        #pragma unroll
        for (int l = 0; l < 3; l++) {
            g_hb[l][0][idx] = __float2bfloat16_rn(0.0f);
            g_c[l][idx] = 0.0f;
        }
    }
    for (int idx = gid; idx < Bsz * Tsz; idx += GT)
        ((__nv_bfloat16*)g_tagsb)[idx] = __float2bfloat16_rn(tags[idx]);
    {
        const float* WihA[3] = {Wih0, Wih1, Wih2};
        const float* WhhA[3] = {Whh0, Whh1, Whh2};
        for (int idx = gid; idx < 3 * G4 * 768; idx += GT) {
            int l   = idx / (G4 * 768);
            int rem = idx - l * (G4 * 768);
            int rp  = rem / 768, k = rem - rp * 768;
            int lr  = (rp & 3) * Asz + (rp >> 2);
            float v;
            if (k < Asz) v = (l == 0) ? WihA[0][(size_t)lr * (Asz + Tsz) + k]
                                      : WihA[l][(size_t)lr * Asz + k];
            else         v = WhhA[l][(size_t)lr * Asz + (k - Asz)];
            ((__nv_bfloat16*)g_Wcomb)[idx] = __float2bfloat16_rn(v);
        }
    }
    for (int idx = gid; idx < G4 * Tsz; idx += GT) {
        int rp = idx / Tsz, k = idx - rp * Tsz;
        int lr = (rp & 3) * Asz + (rp >> 2);
        ((__nv_bfloat16*)g_Wtag)[idx] = __float2bfloat16_rn(Wih0[(size_t)lr * (Asz + Tsz) + Asz + k]);
    }
    for (int idx = gid; idx < Asz * Asz; idx += GT)
        ((__nv_bfloat16*)g_Wlb)[idx] = __float2bfloat16_rn(Wl[idx]);
    {
        const float* bihA[3] = {bih0, bih1, bih2};
        const float* bhhA[3] = {bhh0, bhh1, bhh2};
        for (int idx = gid; idx < 3 * G4; idx += GT) {
            int l = idx / G4, rp = idx - l * G4;
            int lr = (rp & 3) * Asz + (rp >> 2);
            g_biasI[l][rp] = bihA[l][lr] + bhhA[l][lr];
        }
    }
}

// ---------------------------------------------------------------------------
// bf16 mma.sync GEMM, 128x96 CTA tile, 12 warps (32x32 warp tiles),
// KC=128 chunks, 3-stage cp.async pipeline, ldmatrix + fragment double-buffer.
// MODE 0: Cf = acc + biasv            (tagbias build, interleaved cols)
// MODE 1: fused LSTM cell (interleaved gate cols) -> h bf16, c fp32
// MODE 2: sigmoid head -> prevb bf16 + outp fp32
// ---------------------------------------------------------------------------
template<int MODE>
__global__ void __launch_bounds__(NT, 1) gemm_kernel(
    const __nv_bfloat16* __restrict__ X, int ldx, int Kx,
    const __nv_bfloat16* __restrict__ H,                 // nullable; lda=Asz, K=Asz
    const __nv_bfloat16* __restrict__ W, int ldw,
    const float* __restrict__ biasv,
    const float* __restrict__ bmat,
    float* __restrict__ Cf,
    __nv_bfloat16* __restrict__ hout, float* __restrict__ cstate,
    __nv_bfloat16* __restrict__ prevb, float* __restrict__ outp)
{
    extern __shared__ __align__(128) unsigned char dsm[];

    const int m0   = blockIdx.y * TM;
    const int n0   = blockIdx.x * TN;
    const int tid  = threadIdx.x;
    const int warp = tid >> 5;
    const int lane = tid & 31;
    const int wmi  = warp / 3;           // 0..3 (M)
    const int wni  = warp % 3;           // 0..2 (N)
    const int g    = lane >> 2;
    const int tg   = lane & 3;
    const int mi   = lane >> 3;          // ldmatrix matrix id 0..3
    const int lr   = lane & 7;

    const uint32_t sb = smem_u32(dsm);

    float acc[2][4][4];
    #pragma unroll
    for (int ms = 0; ms < 2; ms++)
        #pragma unroll
        for (int ns = 0; ns < 4; ns++)
            #pragma unroll
            for (int r = 0; r < 4; r++) acc[ms][ns][r] = 0.0f;

    const int ncx = Kx / KC;
    const int nc  = ncx + ((H != nullptr) ? (Asz / KC) : 0);

    auto fill = [&](int c) {
        const int buf = c % NSTG;
        const __nv_bfloat16* Asrc;
        int la, kb;
        if (c < ncx) { Asrc = X; la = ldx; kb = c * KC; }
        else         { Asrc = H; la = Asz; kb = (c - ncx) * KC; }
        const uint32_t sA = sb + buf * STAGE;
        const uint32_t sW = sA + TM * ROWB;
        // A: 128 rows x 16 segs = 2048; W: 96 rows x 16 segs = 1536; total 3584
        #pragma unroll
        for (int i = 0; i < 10; i++) {
            int f = tid + i * NT;
            if (f < NSEG) {
                int row = f >> 4, seg = f & 15;
                if (row < TM) {
                    cpa16(sA + row * ROWB + seg * 16,
                          Asrc + (size_t)(m0 + row) * la + kb + seg * 8);
                } else {
                    int wr = row - TM;
                    cpa16(sW + wr * ROWB + seg * 16,
                          W + (size_t)(n0 + wr) * ldw + c * KC + seg * 8);
                }
            }
        }
        CP_COMMIT();
    };

    auto compute = [&](int buf) {
        const uint32_t sA = sb + buf * STAGE;
        const uint32_t sW = sA + TM * ROWB;
        // ldmatrix lane base addresses (matrix order [r0k0, r8k0, r0k8, r8k8])
        const uint32_t aB = sA + (wmi * 32 + (mi & 1) * 8 + lr) * ROWB + (mi >> 1) * 16;
        const uint32_t wB = sW + (wni * 32 + (mi & 1) * 8 + lr) * ROWB + (mi >> 1) * 16;

        uint32_t a0[2][4], a1[2][4], b0[2][4], b1[2][4];
        ldsm_x4(a0[0], aB);
        ldsm_x4(a1[0], aB + 16 * ROWB);
        ldsm_x4(b0[0], wB);
        ldsm_x4(b1[0], wB + 16 * ROWB);
        #pragma unroll
        for (int kt = 0; kt < 8; kt++) {       // 8 x k16 per chunk
            const int cu = kt & 1, nx = cu ^ 1;
            if (kt < 7) {
                ldsm_x4(a0[nx], aB + (kt + 1) * 32);
                ldsm_x4(a1[nx], aB + 16 * ROWB + (kt + 1) * 32);
                ldsm_x4(b0[nx], wB + (kt + 1) * 32);
                ldsm_x4(b1[nx], wB + 16 * ROWB + (kt + 1) * 32);
            }
            mma_bf16(acc[0][0], a0[cu], b0[cu][0], b0[cu][2]);
            mma_bf16(acc[1][0], a1[cu], b0[cu][0], b0[cu][2]);
            mma_bf16(acc[0][1], a0[cu], b0[cu][1], b0[cu][3]);
            mma_bf16(acc[1][1], a1[cu], b0[cu][1], b0[cu][3]);
            mma_bf16(acc[0][2], a0[cu], b1[cu][0], b1[cu][2]);
            mma_bf16(acc[1][2], a1[cu], b1[cu][0], b1[cu][2]);
            mma_bf16(acc[0][3], a0[cu], b1[cu][1], b1[cu][3]);
            mma_bf16(acc[1][3], a1[cu], b1[cu][1], b1[cu][3]);
        }
    };

    fill(0);
    if (nc > 1) fill(1);
    for (int c = 0; c < nc; c++) {
        if (c + 1 < nc) cp_wait<1>(); else cp_wait<0>();
        __syncthreads();
        if (c + 2 < nc) fill(c + 2);
        compute(c % NSTG);
    }

    // ---- Epilogue ----
    #pragma unroll
    for (int ms = 0; ms < 2; ms++) {
        const int r = m0 + wmi * 32 + ms * 16 + g;
        #pragma unroll
        for (int ns = 0; ns < 4; ns++) {
            const int c0 = n0 + wni * 32 + ns * 8 + 2 * tg;
            float v00 = acc[ms][ns][0], v01 = acc[ms][ns][1];
            float v10 = acc[ms][ns][2], v11 = acc[ms][ns][3];
            if (biasv) {
                float bb0 = biasv[c0], bb1 = biasv[c0 + 1];
                v00 += bb0; v01 += bb1; v10 += bb0; v11 += bb1;
            }
            if (MODE == 0) {
                Cf[(size_t)r * G4 + c0]           = v00;
                Cf[(size_t)r * G4 + c0 + 1]       = v01;
                Cf[(size_t)(r + 8) * G4 + c0]     = v10;
                Cf[(size_t)(r + 8) * G4 + c0 + 1] = v11;
            } else if (MODE == 1) {
                if (bmat) {
                    v00 += bmat[(size_t)r * G4 + c0];
                    v01 += bmat[(size_t)r * G4 + c0 + 1];
                    v10 += bmat[(size_t)(r + 8) * G4 + c0];
                    v11 += bmat[(size_t)(r + 8) * G4 + c0 + 1];
                }
                // interleaved cols: even tg lanes hold (i,f); xor-1 partner holds (g,o)
                float p00 = __shfl_xor_sync(0xffffffffu, v00, 1);
                float p01 = __shfl_xor_sync(0xffffffffu, v01, 1);
                float p10 = __shfl_xor_sync(0xffffffffu, v10, 1);
                float p11 = __shfl_xor_sync(0xffffffffu, v11, 1);
                if ((tg & 1) == 0) {
                    const int n = c0 >> 2;
                    {
                        float cold = cstate[(size_t)r * Asz + n];
                        float c2 = sigf(v01) * cold + sigf(v00) * tanhf_fast(p00);
                        cstate[(size_t)r * Asz + n] = c2;
                        hout[(size_t)r * Asz + n] = __float2bfloat16_rn(sigf(p01) * tanhf_fast(c2));
                    }
                    {
                        float cold = cstate[(size_t)(r + 8) * Asz + n];
                        float c2 = sigf(v11) * cold + sigf(v10) * tanhf_fast(p10);
                        cstate[(size_t)(r + 8) * Asz + n] = c2;
                        hout[(size_t)(r + 8) * Asz + n] = __float2bfloat16_rn(sigf(p11) * tanhf_fast(c2));
                    }
                }
            } else { // MODE 2
                v00 = sigf(v00); v01 = sigf(v01); v10 = sigf(v10); v11 = sigf(v11);
                prevb[(size_t)r * Asz + c0]           = __float2bfloat16_rn(v00);
                prevb[(size_t)r * Asz + c0 + 1]       = __float2bfloat16_rn(v01);
                prevb[(size_t)(r + 8) * Asz + c0]     = __float2bfloat16_rn(v10);
                prevb[(size_t)(r + 8) * Asz + c0 + 1] = __float2bfloat16_rn(v11);
                outp[(size_t)r * OUTLD + c0]           = v00;
                outp[(size_t)r * OUTLD + c0 + 1]       = v01;
                outp[(size_t)(r + 8) * OUTLD + c0]     = v10;
                outp[(size_t)(r + 8) * OUTLD + c0 + 1] = v11;
            }
        }
    }
}

// ---------------------------------------------------------------------------
// Launch sequence (graph-capturable: kernel launches only)
// ---------------------------------------------------------------------------
extern "C" void kernel_launch(void* const* d_in, const int* in_sizes, int n_in,
                              void* d_out, int out_size)
{
    const float* tags = (const float*)d_in[2];
    const float* Wih0 = (const float*)d_in[4];
    const float* Whh0 = (const float*)d_in[5];
    const float* bih0 = (const float*)d_in[6];
    const float* bhh0 = (const float*)d_in[7];
    const float* Wih1 = (const float*)d_in[8];
    const float* Whh1 = (const float*)d_in[9];
    const float* bih1 = (const float*)d_in[10];
    const float* bhh1 = (const float*)d_in[11];
    const float* Wih2 = (const float*)d_in[12];
    const float* Whh2 = (const float*)d_in[13];
    const float* bih2 = (const float*)d_in[14];
    const float* bhh2 = (const float*)d_in[15];
    const float* Wl   = (const float*)d_in[16];
    const float* bl   = (const float*)d_in[17];
    float* out = (float*)d_out;

    __nv_bfloat16 *p_tagsb, *p_Wtag, *p_Wcomb, *p_Wlb, *p_hb, *p_prevb;
    float *p_tb, *p_c, *p_bI;
    cudaGetSymbolAddress((void**)&p_tagsb, g_tagsb);
    cudaGetSymbolAddress((void**)&p_Wtag,  g_Wtag);
    cudaGetSymbolAddress((void**)&p_Wcomb, g_Wcomb);
    cudaGetSymbolAddress((void**)&p_Wlb,   g_Wlb);
    cudaGetSymbolAddress((void**)&p_hb,    g_hb);
    cudaGetSymbolAddress((void**)&p_prevb, g_prevb);
    cudaGetSymbolAddress((void**)&p_tb,    g_tagbias);
    cudaGetSymbolAddress((void**)&p_c,     g_c);
    cudaGetSymbolAddress((void**)&p_bI,    g_biasI);

    auto hb   = [&](int l, int pp) { return p_hb + ((size_t)l * 2 + pp) * BA; };
    auto prv_ = [&](int pp)        { return p_prevb + (size_t)pp * BA; };

    cudaFuncSetAttribute(gemm_kernel<0>, cudaFuncAttributeMaxDynamicSharedMemorySize, SMEMB);
    cudaFuncSetAttribute(gemm_kernel<1>, cudaFuncAttributeMaxDynamicSharedMemorySize, SMEMB);
    cudaFuncSetAttribute(gemm_kernel<2>, cudaFuncAttributeMaxDynamicSharedMemorySize, SMEMB);

    const dim3 gridFull(G4 / TN, Bsz / TM);   // (16, 8) = 128 CTAs
    const dim3 gridHead(Asz / TN, Bsz / TM);  // (4, 8)  = 32 CTAs

    // 1) prep
    prep_kernel<<<1024, 256>>>(tags, Wih0, Whh0, bih0, bhh0,
                               Wih1, Whh1, bih1, bhh1,
                               Wih2, Whh2, bih2, bhh2, Wl, out);

    // 2) tagbias = tags @ Wtag^T + biasI[0]  (Kx = Tsz = 128 -> 1 chunk)
    gemm_kernel<0><<<gridFull, NT, SMEMB>>>(p_tagsb, Tsz, Tsz, nullptr,
                                            p_Wtag, Tsz,
                                            p_bI, nullptr,
                                            p_tb, nullptr, nullptr, nullptr, nullptr);

    // 3) 49 recurrent steps
    for (int t = 1; t < Lsz; t++) {
        const int cur = t & 1, prv = cur ^ 1;

        gemm_kernel<1><<<gridFull, NT, SMEMB>>>(prv_(prv), Asz, Asz, hb(0, prv),
                                                p_Wcomb + 0 * (size_t)G4 * 768, 768,
                                                nullptr, p_tb,
                                                nullptr, hb(0, cur), p_c + 0 * BA,
                                                nullptr, nullptr);

        gemm_kernel<1><<<gridFull, NT, SMEMB>>>(hb(0, cur), Asz, Asz, hb(1, prv),
                                                p_Wcomb + 1 * (size_t)G4 * 768, 768,
                                                p_bI + G4, nullptr,
                                                nullptr, hb(1, cur), p_c + 1 * BA,
                                                nullptr, nullptr);

        gemm_kernel<1><<<gridFull, NT, SMEMB>>>(hb(1, cur), Asz, Asz, hb(2, prv),
                                                p_Wcomb + 2 * (size_t)G4 * 768, 768,
                                                p_bI + 2 * G4, nullptr,
                                                nullptr, hb(2, cur), p_c + 2 * BA,
                                                nullptr, nullptr);

        gemm_kernel<2><<<gridHead, NT, SMEMB>>>(hb(2, cur), Asz, Asz, nullptr,
                                                p_Wlb, Asz,
                                                bl, nullptr,
                                                nullptr, nullptr, nullptr,
                                                prv_(cur), out + (size_t)t * Asz);
    }
}

// round 11
// speedup vs baseline: 1.0988x; 1.0988x over previous
#include <cuda_runtime.h>
#include <cuda_bf16.h>
#include <math.h>
#include <stdint.h>

// Problem constants
#define Asz   384
#define Tsz   128
#define Bsz   1024
#define Lsz   50
#define G4    1536
#define BA    (Bsz*Asz)
#define OUTLD (Lsz*Asz)

// GEMM tiling (R6-proven config)
#define TM    128
#define TN    96
#define KC    64            // bf16 K elems per chunk (128B payload per row)
#define ROWB  144           // smem row stride bytes (128 payload + 16 pad)
#define NT    384           // 12 warps: 4(M) x 3(N), warp tile 32x32
#define NSTG  3
#define STAGE ((TM + TN) * ROWB)       // 32256 B
#define SMEMB (NSTG * STAGE)           // 96768 B (1 CTA/SM, single wave)
#define NCTA  128

typedef __nv_bfloat16 bf16;

// ---------------------------------------------------------------------------
// Device scratch
// ---------------------------------------------------------------------------
__device__ __align__(128) bf16 g_Wcomb[3][G4][768]; // gate-interleaved rows: [x(384) | h(384)]
__device__ __align__(128) bf16 g_Wtag[G4][Tsz];     // gate-interleaved rows, tag slice
__device__ __align__(128) bf16 g_Wlb[Asz][Asz];
__device__ __align__(128) bf16 g_tagsb[Bsz][Tsz];
__device__ __align__(128) bf16 g_hb[3][2][BA];
__device__ __align__(128) bf16 g_prevb[2][BA];
__device__ __align__(128) float g_c[3][BA];
__device__ __align__(128) float g_tagbias[Bsz * G4];
__device__ __align__(128) float g_biasI[3][G4];
__device__ unsigned long long g_cnt;

__device__ __forceinline__ float sigf(float x) { return 1.0f / (1.0f + __expf(-x)); }
__device__ __forceinline__ float tanhf_fast(float x) { return 2.0f / (1.0f + __expf(-2.0f * x)) - 1.0f; }

// ---------------------------------------------------------------------------
// PTX helpers
// ---------------------------------------------------------------------------
__device__ __forceinline__ uint32_t smem_u32(const void* p)
{
    uint32_t a;
    asm("{ .reg .u64 t; cvta.to.shared.u64 t, %1; cvt.u32.u64 %0, t; }" : "=r"(a) : "l"(p));
    return a;
}

__device__ __forceinline__ void cpa16(uint32_t s, const void* g)
{
    asm volatile("cp.async.cg.shared.global [%0], [%1], 16;" :: "r"(s), "l"(g));
}
#define CP_COMMIT()  asm volatile("cp.async.commit_group;")
template<int N>
__device__ __forceinline__ void cp_wait() { asm volatile("cp.async.wait_group %0;" :: "n"(N) : "memory"); }

__device__ __forceinline__ void ldsm_x4(uint32_t r[4], uint32_t addr)
{
    asm volatile("ldmatrix.sync.aligned.m8n8.x4.shared.b16 {%0,%1,%2,%3}, [%4];"
        : "=r"(r[0]), "=r"(r[1]), "=r"(r[2]), "=r"(r[3]) : "r"(addr));
}

__device__ __forceinline__ void mma_bf16(float c[4], const uint32_t a[4], const uint32_t b0, const uint32_t b1)
{
    asm volatile(
        "mma.sync.aligned.m16n8k16.row.col.f32.bf16.bf16.f32 "
        "{%0,%1,%2,%3},{%4,%5,%6,%7},{%8,%9},{%0,%1,%2,%3};"
        : "+f"(c[0]), "+f"(c[1]), "+f"(c[2]), "+f"(c[3])
        : "r"(a[0]), "r"(a[1]), "r"(a[2]), "r"(a[3]), "r"(b0), "r"(b1));
}

// ---------------------------------------------------------------------------
// Prep + reset
// ---------------------------------------------------------------------------
__global__ void reset_kernel() { g_cnt = 0ULL; }

__global__ void prep_kernel(
    const float* __restrict__ tags,
    const float* __restrict__ Wih0, const float* __restrict__ Whh0,
    const float* __restrict__ bih0, const float* __restrict__ bhh0,
    const float* __restrict__ Wih1, const float* __restrict__ Whh1,
    const float* __restrict__ bih1, const float* __restrict__ bhh1,
    const float* __restrict__ Wih2, const float* __restrict__ Whh2,
    const float* __restrict__ bih2, const float* __restrict__ bhh2,
    const float* __restrict__ Wl,
    float* __restrict__ out)
{
    const int gid = blockIdx.x * blockDim.x + threadIdx.x;
    const int GT  = gridDim.x * blockDim.x;

    for (int idx = gid; idx < BA; idx += GT) {
        int m = idx / Asz, n = idx - m * Asz;
        float v = (n == 1) ? 1.0f : 0.0f;   // START = 1
        out[(size_t)m * OUTLD + n] = v;
        g_prevb[0][idx] = __float2bfloat16_rn(v);
        #pragma unroll
        for (int l = 0; l < 3; l++) {
            g_hb[l][0][idx] = __float2bfloat16_rn(0.0f);
            g_c[l][idx] = 0.0f;
        }
    }
    for (int idx = gid; idx < Bsz * Tsz; idx += GT)
        ((bf16*)g_tagsb)[idx] = __float2bfloat16_rn(tags[idx]);
    {
        const float* WihA[3] = {Wih0, Wih1, Wih2};
        const float* WhhA[3] = {Whh0, Whh1, Whh2};
        for (int idx = gid; idx < 3 * G4 * 768; idx += GT) {
            int l   = idx / (G4 * 768);
            int rem = idx - l * (G4 * 768);
            int rp  = rem / 768, k = rem - rp * 768;
            int lr  = (rp & 3) * Asz + (rp >> 2);
            float v;
            if (k < Asz) v = (l == 0) ? WihA[0][(size_t)lr * (Asz + Tsz) + k]
                                      : WihA[l][(size_t)lr * Asz + k];
            else         v = WhhA[l][(size_t)lr * Asz + (k - Asz)];
            ((bf16*)g_Wcomb)[idx] = __float2bfloat16_rn(v);
        }
    }
    for (int idx = gid; idx < G4 * Tsz; idx += GT) {
        int rp = idx / Tsz, k = idx - rp * Tsz;
        int lr = (rp & 3) * Asz + (rp >> 2);
        ((bf16*)g_Wtag)[idx] = __float2bfloat16_rn(Wih0[(size_t)lr * (Asz + Tsz) + Asz + k]);
    }
    for (int idx = gid; idx < Asz * Asz; idx += GT)
        ((bf16*)g_Wlb)[idx] = __float2bfloat16_rn(Wl[idx]);
    {
        const float* bihA[3] = {bih0, bih1, bih2};
        const float* bhhA[3] = {bhh0, bhh1, bhh2};
        for (int idx = gid; idx < 3 * G4; idx += GT) {
            int l = idx / G4, rp = idx - l * G4;
            int lr = (rp & 3) * Asz + (rp >> 2);
            g_biasI[l][rp] = bihA[l][lr] + bhhA[l][lr];
        }
    }
}

// ---------------------------------------------------------------------------
// Shared GEMM building blocks (R6-proven layout)
// ---------------------------------------------------------------------------
__device__ __forceinline__ void fill_chunk(
    uint32_t sb, int tid, int buf,
    const bf16* __restrict__ Asrc, int la, int ka,
    const bf16* __restrict__ W, int ldw, int wk, int n0, int m0)
{
    const uint32_t sA = sb + buf * STAGE;
    const uint32_t sW = sA + TM * ROWB;
    #pragma unroll
    for (int i = 0; i < 3; i++) {              // A: 128 rows x 8 segs = 1024
        int f = tid + i * NT;
        if (f < TM * 8) {
            int row = f >> 3, seg = f & 7;
            cpa16(sA + row * ROWB + seg * 16,
                  Asrc + (size_t)(m0 + row) * la + ka + seg * 8);
        }
    }
    #pragma unroll
    for (int i = 0; i < 2; i++) {              // W: 96 rows x 8 segs = 768
        int f = tid + i * NT;
        int row = f >> 3, seg = f & 7;
        cpa16(sW + row * ROWB + seg * 16,
              W + (size_t)(n0 + row) * ldw + wk + seg * 8);
    }
    CP_COMMIT();
}

// One GEMM phase. MODE 0: tagbias; MODE 1: fused LSTM; MODE 2: sigmoid head.
// If self_prologue==false, chunks 0,1 must already be in flight (2 groups).
template<int MODE>
__device__ __forceinline__ void phase_gemm(
    uint32_t sb, int tid, int m0, int n0,
    const bf16* __restrict__ X, int ldx, int nc, int nch,
    const bf16* __restrict__ H,
    const bf16* __restrict__ W, int ldw, int wkH,
    const float* __restrict__ biasv, const float* __restrict__ bmat,
    float* __restrict__ Cf,
    bf16* __restrict__ hout, float* __restrict__ cstate,
    bf16* __restrict__ prevb, float* __restrict__ outp,
    bool self_prologue)
{
    const int warp = tid >> 5;
    const int lane = tid & 31;
    const int wmi  = warp / 3;           // 0..3 (M)
    const int wni  = warp % 3;           // 0..2 (N)
    const int g    = lane >> 2;
    const int tg   = lane & 3;
    const int mi   = lane >> 3;
    const int lr   = lane & 7;

    float acc[2][4][4];
    #pragma unroll
    for (int ms = 0; ms < 2; ms++)
        #pragma unroll
        for (int ns = 0; ns < 4; ns++)
            #pragma unroll
            for (int r = 0; r < 4; r++) acc[ms][ns][r] = 0.0f;

    auto fill = [&](int c) {
        const bf16* Ab; int la, ka, wk;
        if (c < nch) { Ab = H; la = Asz; ka = c * KC; wk = wkH + c * KC; }
        else         { Ab = X; la = ldx; ka = (c - nch) * KC; wk = (c - nch) * KC; }
        fill_chunk(sb, tid, c % NSTG, Ab, la, ka, W, ldw, wk, n0, m0);
    };

    auto compute = [&](int buf) {
        const uint32_t sA = sb + buf * STAGE;
        const uint32_t sW = sA + TM * ROWB;
        const uint32_t aB = sA + (wmi * 32 + (mi & 1) * 8 + lr) * ROWB + (mi >> 1) * 16;
        const uint32_t wB = sW + (wni * 32 + (mi & 1) * 8 + lr) * ROWB + (mi >> 1) * 16;
        #pragma unroll
        for (int kt = 0; kt < 4; kt++) {
            uint32_t a0[4], a1[4], b0[4], b1[4];
            ldsm_x4(a0, aB + kt * 32);
            ldsm_x4(a1, aB + 16 * ROWB + kt * 32);
            ldsm_x4(b0, wB + kt * 32);
            ldsm_x4(b1, wB + 16 * ROWB + kt * 32);
            mma_bf16(acc[0][0], a0, b0[0], b0[2]);
            mma_bf16(acc[1][0], a1, b0[0], b0[2]);
            mma_bf16(acc[0][1], a0, b0[1], b0[3]);
            mma_bf16(acc[1][1], a1, b0[1], b0[3]);
            mma_bf16(acc[0][2], a0, b1[0], b1[2]);
            mma_bf16(acc[1][2], a1, b1[0], b1[2]);
            mma_bf16(acc[0][3], a0, b1[1], b1[3]);
            mma_bf16(acc[1][3], a1, b1[1], b1[3]);
        }
    };

    if (self_prologue) { fill(0); if (nc > 1) fill(1); }

    for (int c = 0; c < nc; c++) {
        if (c + 1 < nc) cp_wait<1>(); else cp_wait<0>();
        __syncthreads();
        if (c + 2 < nc) fill(c + 2);
        compute(c % NSTG);
    }

    // ---- Epilogue ----
    #pragma unroll
    for (int ms = 0; ms < 2; ms++) {
        const int r = m0 + wmi * 32 + ms * 16 + g;
        #pragma unroll
        for (int ns = 0; ns < 4; ns++) {
            const int c0 = n0 + wni * 32 + ns * 8 + 2 * tg;
            float v00 = acc[ms][ns][0], v01 = acc[ms][ns][1];
            float v10 = acc[ms][ns][2], v11 = acc[ms][ns][3];
            if (biasv) {
                float bb0 = biasv[c0], bb1 = biasv[c0 + 1];
                v00 += bb0; v01 += bb1; v10 += bb0; v11 += bb1;
            }
            if (MODE == 0) {
                Cf[(size_t)r * G4 + c0]           = v00;
                Cf[(size_t)r * G4 + c0 + 1]       = v01;
                Cf[(size_t)(r + 8) * G4 + c0]     = v10;
                Cf[(size_t)(r + 8) * G4 + c0 + 1] = v11;
            } else if (MODE == 1) {
                if (bmat) {
                    v00 += bmat[(size_t)r * G4 + c0];
                    v01 += bmat[(size_t)r * G4 + c0 + 1];
                    v10 += bmat[(size_t)(r + 8) * G4 + c0];
                    v11 += bmat[(size_t)(r + 8) * G4 + c0 + 1];
                }
                float p00 = __shfl_xor_sync(0xffffffffu, v00, 1);
                float p01 = __shfl_xor_sync(0xffffffffu, v01, 1);
                float p10 = __shfl_xor_sync(0xffffffffu, v10, 1);
                float p11 = __shfl_xor_sync(0xffffffffu, v11, 1);
                if ((tg & 1) == 0) {
                    const int n = c0 >> 2;
                    {
                        float cold = cstate[(size_t)r * Asz + n];
                        float c2 = sigf(v01) * cold + sigf(v00) * tanhf_fast(p00);
                        cstate[(size_t)r * Asz + n] = c2;
                        hout[(size_t)r * Asz + n] = __float2bfloat16_rn(sigf(p01) * tanhf_fast(c2));
                    }
                    {
                        float cold = cstate[(size_t)(r + 8) * Asz + n];
                        float c2 = sigf(v11) * cold + sigf(v10) * tanhf_fast(p10);
                        cstate[(size_t)(r + 8) * Asz + n] = c2;
                        hout[(size_t)(r + 8) * Asz + n] = __float2bfloat16_rn(sigf(p11) * tanhf_fast(c2));
                    }
                }
            } else { // MODE 2
                v00 = sigf(v00); v01 = sigf(v01); v10 = sigf(v10); v11 = sigf(v11);
                prevb[(size_t)r * Asz + c0]           = __float2bfloat16_rn(v00);
                prevb[(size_t)r * Asz + c0 + 1]       = __float2bfloat16_rn(v01);
                prevb[(size_t)(r + 8) * Asz + c0]     = __float2bfloat16_rn(v10);
                prevb[(size_t)(r + 8) * Asz + c0 + 1] = __float2bfloat16_rn(v11);
                outp[(size_t)r * OUTLD + c0]           = v00;
                outp[(size_t)r * OUTLD + c0 + 1]       = v01;
                outp[(size_t)(r + 8) * OUTLD + c0]     = v10;
                outp[(size_t)(r + 8) * OUTLD + c0 + 1] = v11;
            }
        }
    }
}

// ---------------------------------------------------------------------------
// tagbias kernel (standalone MODE0, grid (16,8))
// ---------------------------------------------------------------------------
__global__ void __launch_bounds__(NT) tag_kernel()
{
    extern __shared__ __align__(128) unsigned char dsm[];
    const uint32_t sb = smem_u32(dsm);
    phase_gemm<0>(sb, threadIdx.x, blockIdx.y * TM, blockIdx.x * TN,
                  (const bf16*)g_tagsb, Tsz, Tsz / KC, 0,
                  nullptr, (const bf16*)g_Wtag, Tsz, 0,
                  g_biasI[0], nullptr,
                  g_tagbias, nullptr, nullptr, nullptr, nullptr, true);
}

// ---------------------------------------------------------------------------
// Persistent whole-sequence kernel (128 CTAs, single wave, bounded-spin barrier)
// ---------------------------------------------------------------------------
__global__ void __launch_bounds__(NT) seq_kernel(const float* __restrict__ bl,
                                                 float* __restrict__ out)
{
    extern __shared__ __align__(128) unsigned char dsm[];
    const uint32_t sb = smem_u32(dsm);
    const int tid = threadIdx.x;
    const int bx  = blockIdx.x;
    unsigned long long bk = 0;

    auto gbar = [&]() {
        __syncthreads();
        if (tid == 0) {
            __threadfence();
            atomicAdd(&g_cnt, 1ULL);
            const unsigned long long target = (unsigned long long)NCTA * bk;
            int guard = 0;
            while (*(volatile unsigned long long*)&g_cnt < target) {
                __nanosleep(64);
                if (++guard > 10000000) break;   // watchdog: fail fast, never hang
            }
            __threadfence();
        }
        __syncthreads();
    };

    // prefill chunks 0,1 (always the H-half of the next layer phase)
    auto prefill2 = [&](const bf16* H, const bf16* W, int n0, int m0) {
        fill_chunk(sb, tid, 0, H, Asz, 0,  W, 768, Asz,      n0, m0);
        fill_chunk(sb, tid, 1, H, Asz, KC, W, 768, Asz + KC, n0, m0);
    };

    const int n0F = (bx & 15) * TN;      // layer tile (fixed -> c ownership stable)
    const int m0F = (bx >> 4) * TM;

    // initial prefill for L0(t=1): H = h0(prv=0)
    prefill2(g_hb[0][0], (const bf16*)g_Wcomb[0], n0F, m0F);

    for (int t = 1; t < Lsz; t++) {
        const int cur = t & 1, prv = cur ^ 1;

        // layer 0
        phase_gemm<1>(sb, tid, m0F, n0F,
                      g_prevb[prv], Asz, 12, 6,
                      g_hb[0][prv], (const bf16*)g_Wcomb[0], 768, Asz,
                      nullptr, g_tagbias,
                      nullptr, g_hb[0][cur], g_c[0], nullptr, nullptr, false);
        prefill2(g_hb[1][prv], (const bf16*)g_Wcomb[1], n0F, m0F);
        bk++; gbar();

        // layer 1
        phase_gemm<1>(sb, tid, m0F, n0F,
                      g_hb[0][cur], Asz, 12, 6,
                      g_hb[1][prv], (const bf16*)g_Wcomb[1], 768, Asz,
                      g_biasI[1], nullptr,
                      nullptr, g_hb[1][cur], g_c[1], nullptr, nullptr, false);
        prefill2(g_hb[2][prv], (const bf16*)g_Wcomb[2], n0F, m0F);
        bk++; gbar();

        // layer 2 (no prefill: head's X not published yet)
        phase_gemm<1>(sb, tid, m0F, n0F,
                      g_hb[1][cur], Asz, 12, 6,
                      g_hb[2][prv], (const bf16*)g_Wcomb[2], 768, Asz,
                      g_biasI[2], nullptr,
                      nullptr, g_hb[2][cur], g_c[2], nullptr, nullptr, false);
        bk++; gbar();

        // head (first 32 CTAs), self-prologue
        if (bx < 32) {
            phase_gemm<2>(sb, tid, (bx >> 2) * TM, (bx & 3) * TN,
                          g_hb[2][cur], Asz, 6, 0,
                          nullptr, (const bf16*)g_Wlb, Asz, 0,
                          bl, nullptr,
                          nullptr, nullptr, nullptr,
                          g_prevb[cur], out + (size_t)t * Asz, true);
        }
        if (t + 1 < Lsz)   // prefill L0(t+1): H = h0(t) (published 3 barriers ago)
            prefill2(g_hb[0][cur], (const bf16*)g_Wcomb[0], n0F, m0F);
        bk++; gbar();
    }
}

// ---------------------------------------------------------------------------
// Launch sequence (graph-capturable: 4 kernel nodes)
// ---------------------------------------------------------------------------
extern "C" void kernel_launch(void* const* d_in, const int* in_sizes, int n_in,
                              void* d_out, int out_size)
{
    const float* tags = (const float*)d_in[2];
    const float* Wih0 = (const float*)d_in[4];
    const float* Whh0 = (const float*)d_in[5];
    const float* bih0 = (const float*)d_in[6];
    const float* bhh0 = (const float*)d_in[7];
    const float* Wih1 = (const float*)d_in[8];
    const float* Whh1 = (const float*)d_in[9];
    const float* bih1 = (const float*)d_in[10];
    const float* bhh1 = (const float*)d_in[11];
    const float* Wih2 = (const float*)d_in[12];
    const float* Whh2 = (const float*)d_in[13];
    const float* bih2 = (const float*)d_in[14];
    const float* bhh2 = (const float*)d_in[15];
    const float* Wl   = (const float*)d_in[16];
    const float* bl   = (const float*)d_in[17];
    float* out = (float*)d_out;

    cudaFuncSetAttribute(tag_kernel, cudaFuncAttributeMaxDynamicSharedMemorySize, SMEMB);
    cudaFuncSetAttribute(seq_kernel, cudaFuncAttributeMaxDynamicSharedMemorySize, SMEMB);

    // 1) reset barrier counter
    reset_kernel<<<1, 1>>>();

    // 2) prep: conversions + init
    prep_kernel<<<1024, 256>>>(tags, Wih0, Whh0, bih0, bhh0,
                               Wih1, Whh1, bih1, bhh1,
                               Wih2, Whh2, bih2, bhh2, Wl, out);

    // 3) tagbias = tags @ Wtag^T + biasI[0]
    tag_kernel<<<dim3(G4 / TN, Bsz / TM), NT, SMEMB>>>();

    // 4) persistent sequence
    seq_kernel<<<NCTA, NT, SMEMB>>>(bl, out);
}

// round 15
// speedup vs baseline: 1.1645x; 1.0598x over previous
#include <cuda_runtime.h>
#include <cuda_bf16.h>
#include <math.h>
#include <stdint.h>

// Problem constants
#define Asz   384
#define Tsz   128
#define Bsz   1024
#define Lsz   50
#define G4    1536
#define BA    (Bsz*Asz)
#define OUTLD (Lsz*Asz)

// GEMM tiling (R6-proven config)
#define TM    128
#define TN    96
#define KC    64            // bf16 K elems per chunk (128B payload per row)
#define ROWB  144           // smem row stride bytes (128 payload + 16 pad)
#define NT    384           // 12 warps
#define NSTG  3
#define STAGE ((TM + TN) * ROWB)       // 32256 B
#define SMEMB (NSTG * STAGE)           // 96768 B (1 CTA/SM, single wave)
#define NCTA  128
// Head tiling: 64x48 tiles, 128 tiles -> all CTAs
#define HTM   64
#define HTN   48
#define STGH  ((HTM + HTN) * ROWB)     // 16128 B

typedef __nv_bfloat16 bf16;

// ---------------------------------------------------------------------------
// Device scratch
// ---------------------------------------------------------------------------
__device__ __align__(128) bf16 g_Wcomb[3][G4][768]; // gate-interleaved rows: [x(384) | h(384)]
__device__ __align__(128) bf16 g_Wtag[G4][Tsz];     // gate-interleaved rows, tag slice
__device__ __align__(128) bf16 g_Wlb[Asz][Asz];
__device__ __align__(128) bf16 g_tagsb[Bsz][Tsz];
__device__ __align__(128) bf16 g_hb[3][2][BA];
__device__ __align__(128) bf16 g_prevb[2][BA];
__device__ __align__(128) float g_c[3][BA];
__device__ __align__(128) float g_tagbias[Bsz * G4];
__device__ __align__(128) float g_biasI[3][G4];
__device__ unsigned long long g_cnt;

__device__ __forceinline__ float sigf(float x) { return 1.0f / (1.0f + __expf(-x)); }
__device__ __forceinline__ float tanhf_fast(float x) { return 2.0f / (1.0f + __expf(-2.0f * x)) - 1.0f; }

// ---------------------------------------------------------------------------
// PTX helpers
// ---------------------------------------------------------------------------
__device__ __forceinline__ uint32_t smem_u32(const void* p)
{
    uint32_t a;
    asm("{ .reg .u64 t; cvta.to.shared.u64 t, %1; cvt.u32.u64 %0, t; }" : "=r"(a) : "l"(p));
    return a;
}

__device__ __forceinline__ void cpa16(uint32_t s, const void* g)
{
    asm volatile("cp.async.cg.shared.global [%0], [%1], 16;" :: "r"(s), "l"(g));
}
#define CP_COMMIT()  asm volatile("cp.async.commit_group;")
template<int N>
__device__ __forceinline__ void cp_wait() { asm volatile("cp.async.wait_group %0;" :: "n"(N) : "memory"); }

__device__ __forceinline__ void ldsm_x4(uint32_t r[4], uint32_t addr)
{
    asm volatile("ldmatrix.sync.aligned.m8n8.x4.shared.b16 {%0,%1,%2,%3}, [%4];"
        : "=r"(r[0]), "=r"(r[1]), "=r"(r[2]), "=r"(r[3]) : "r"(addr));
}

__device__ __forceinline__ void ldsm_x2(uint32_t r[2], uint32_t addr)
{
    asm volatile("ldmatrix.sync.aligned.m8n8.x2.shared.b16 {%0,%1}, [%2];"
        : "=r"(r[0]), "=r"(r[1]) : "r"(addr));
}

__device__ __forceinline__ void mma_bf16(float c[4], const uint32_t a[4], const uint32_t b0, const uint32_t b1)
{
    asm volatile(
        "mma.sync.aligned.m16n8k16.row.col.f32.bf16.bf16.f32 "
        "{%0,%1,%2,%3},{%4,%5,%6,%7},{%8,%9},{%0,%1,%2,%3};"
        : "+f"(c[0]), "+f"(c[1]), "+f"(c[2]), "+f"(c[3])
        : "r"(a[0]), "r"(a[1]), "r"(a[2]), "r"(a[3]), "r"(b0), "r"(b1));
}

// ---------------------------------------------------------------------------
// Prep + reset
// ---------------------------------------------------------------------------
__global__ void reset_kernel() { g_cnt = 0ULL; }

__global__ void prep_kernel(
    const float* __restrict__ tags,
    const float* __restrict__ Wih0, const float* __restrict__ Whh0,
    const float* __restrict__ bih0, const float* __restrict__ bhh0,
    const float* __restrict__ Wih1, const float* __restrict__ Whh1,
    const float* __restrict__ bih1, const float* __restrict__ bhh1,
    const float* __restrict__ Wih2, const float* __restrict__ Whh2,
    const float* __restrict__ bih2, const float* __restrict__ bhh2,
    const float* __restrict__ Wl,
    float* __restrict__ out)
{
    const int gid = blockIdx.x * blockDim.x + threadIdx.x;
    const int GT  = gridDim.x * blockDim.x;

    for (int idx = gid; idx < BA; idx += GT) {
        int m = idx / Asz, n = idx - m * Asz;
        float v = (n == 1) ? 1.0f : 0.0f;   // START = 1
        out[(size_t)m * OUTLD + n] = v;
        g_prevb[0][idx] = __float2bfloat16_rn(v);
        #pragma unroll
        for (int l = 0; l < 3; l++) {
            g_hb[l][0][idx] = __float2bfloat16_rn(0.0f);
            g_c[l][idx] = 0.0f;
        }
    }
    for (int idx = gid; idx < Bsz * Tsz; idx += GT)
        ((bf16*)g_tagsb)[idx] = __float2bfloat16_rn(tags[idx]);
    {
        const float* WihA[3] = {Wih0, Wih1, Wih2};
        const float* WhhA[3] = {Whh0, Whh1, Whh2};
        for (int idx = gid; idx < 3 * G4 * 768; idx += GT) {
            int l   = idx / (G4 * 768);
            int rem = idx - l * (G4 * 768);
            int rp  = rem / 768, k = rem - rp * 768;
            int lr  = (rp & 3) * Asz + (rp >> 2);
            float v;
            if (k < Asz) v = (l == 0) ? WihA[0][(size_t)lr * (Asz + Tsz) + k]
                                      : WihA[l][(size_t)lr * Asz + k];
            else         v = WhhA[l][(size_t)lr * Asz + (k - Asz)];
            ((bf16*)g_Wcomb)[idx] = __float2bfloat16_rn(v);
        }
    }
    for (int idx = gid; idx < G4 * Tsz; idx += GT) {
        int rp = idx / Tsz, k = idx - rp * Tsz;
        int lr = (rp & 3) * Asz + (rp >> 2);
        ((bf16*)g_Wtag)[idx] = __float2bfloat16_rn(Wih0[(size_t)lr * (Asz + Tsz) + Asz + k]);
    }
    for (int idx = gid; idx < Asz * Asz; idx += GT)
        ((bf16*)g_Wlb)[idx] = __float2bfloat16_rn(Wl[idx]);
    {
        const float* bihA[3] = {bih0, bih1, bih2};
        const float* bhhA[3] = {bhh0, bhh1, bhh2};
        for (int idx = gid; idx < 3 * G4; idx += GT) {
            int l = idx / G4, rp = idx - l * G4;
            int lr = (rp & 3) * Asz + (rp >> 2);
            g_biasI[l][rp] = bihA[l][lr] + bhhA[l][lr];
        }
    }
}

// ---------------------------------------------------------------------------
// Shared GEMM building blocks (R6-proven layout)
// ---------------------------------------------------------------------------
__device__ __forceinline__ void fill_chunk(
    uint32_t sb, int tid, int buf,
    const bf16* __restrict__ Asrc, int la, int ka,
    const bf16* __restrict__ W, int ldw, int wk, int n0, int m0)
{
    const uint32_t sA = sb + buf * STAGE;
    const uint32_t sW = sA + TM * ROWB;
    #pragma unroll
    for (int i = 0; i < 3; i++) {              // A: 128 rows x 8 segs = 1024
        int f = tid + i * NT;
        if (f < TM * 8) {
            int row = f >> 3, seg = f & 7;
            cpa16(sA + row * ROWB + seg * 16,
                  Asrc + (size_t)(m0 + row) * la + ka + seg * 8);
        }
    }
    #pragma unroll
    for (int i = 0; i < 2; i++) {              // W: 96 rows x 8 segs = 768
        int f = tid + i * NT;
        int row = f >> 3, seg = f & 7;
        cpa16(sW + row * ROWB + seg * 16,
              W + (size_t)(n0 + row) * ldw + wk + seg * 8);
    }
    CP_COMMIT();
}

// One GEMM phase. MODE 0: tagbias; MODE 1: fused LSTM.
template<int MODE>
__device__ __forceinline__ void phase_gemm(
    uint32_t sb, int tid, int m0, int n0,
    const bf16* __restrict__ X, int ldx, int nc, int nch,
    const bf16* __restrict__ H,
    const bf16* __restrict__ W, int ldw, int wkH,
    const float* __restrict__ biasv, const float* __restrict__ bmat,
    float* __restrict__ Cf,
    bf16* __restrict__ hout, float* __restrict__ cstate,
    bool self_prologue)
{
    const int warp = tid >> 5;
    const int lane = tid & 31;
    const int wmi  = warp / 3;           // 0..3 (M)
    const int wni  = warp % 3;           // 0..2 (N)
    const int g    = lane >> 2;
    const int tg   = lane & 3;
    const int mi   = lane >> 3;
    const int lr   = lane & 7;

    float acc[2][4][4];
    #pragma unroll
    for (int ms = 0; ms < 2; ms++)
        #pragma unroll
        for (int ns = 0; ns < 4; ns++)
            #pragma unroll
            for (int r = 0; r < 4; r++) acc[ms][ns][r] = 0.0f;

    auto fill = [&](int c) {
        const bf16* Ab; int la, ka, wk;
        if (c < nch) { Ab = H; la = Asz; ka = c * KC; wk = wkH + c * KC; }
        else         { Ab = X; la = ldx; ka = (c - nch) * KC; wk = (c - nch) * KC; }
        fill_chunk(sb, tid, c % NSTG, Ab, la, ka, W, ldw, wk, n0, m0);
    };

    auto compute = [&](int buf) {
        const uint32_t sA = sb + buf * STAGE;
        const uint32_t sW = sA + TM * ROWB;
        const uint32_t aB = sA + (wmi * 32 + (mi & 1) * 8 + lr) * ROWB + (mi >> 1) * 16;
        const uint32_t wB = sW + (wni * 32 + (mi & 1) * 8 + lr) * ROWB + (mi >> 1) * 16;
        #pragma unroll
        for (int kt = 0; kt < 4; kt++) {
            uint32_t a0[4], a1[4], b0[4], b1[4];
            ldsm_x4(a0, aB + kt * 32);
            ldsm_x4(a1, aB + 16 * ROWB + kt * 32);
            ldsm_x4(b0, wB + kt * 32);
            ldsm_x4(b1, wB + 16 * ROWB + kt * 32);
            mma_bf16(acc[0][0], a0, b0[0], b0[2]);
            mma_bf16(acc[1][0], a1, b0[0], b0[2]);
            mma_bf16(acc[0][1], a0, b0[1], b0[3]);
            mma_bf16(acc[1][1], a1, b0[1], b0[3]);
            mma_bf16(acc[0][2], a0, b1[0], b1[2]);
            mma_bf16(acc[1][2], a1, b1[0], b1[2]);
            mma_bf16(acc[0][3], a0, b1[1], b1[3]);
            mma_bf16(acc[1][3], a1, b1[1], b1[3]);
        }
    };

    if (self_prologue) { fill(0); if (nc > 1) fill(1); }

    for (int c = 0; c < nc; c++) {
        if (c + 1 < nc) cp_wait<1>(); else cp_wait<0>();
        __syncthreads();
        if (c + 2 < nc) fill(c + 2);
        compute(c % NSTG);
    }

    // ---- Epilogue ----
    #pragma unroll
    for (int ms = 0; ms < 2; ms++) {
        const int r = m0 + wmi * 32 + ms * 16 + g;
        #pragma unroll
        for (int ns = 0; ns < 4; ns++) {
            const int c0 = n0 + wni * 32 + ns * 8 + 2 * tg;
            float v00 = acc[ms][ns][0], v01 = acc[ms][ns][1];
            float v10 = acc[ms][ns][2], v11 = acc[ms][ns][3];
            if (biasv) {
                float bb0 = biasv[c0], bb1 = biasv[c0 + 1];
                v00 += bb0; v01 += bb1; v10 += bb0; v11 += bb1;
            }
            if (MODE == 0) {
                Cf[(size_t)r * G4 + c0]           = v00;
                Cf[(size_t)r * G4 + c0 + 1]       = v01;
                Cf[(size_t)(r + 8) * G4 + c0]     = v10;
                Cf[(size_t)(r + 8) * G4 + c0 + 1] = v11;
            } else {
                if (bmat) {
                    v00 += bmat[(size_t)r * G4 + c0];
                    v01 += bmat[(size_t)r * G4 + c0 + 1];
                    v10 += bmat[(size_t)(r + 8) * G4 + c0];
                    v11 += bmat[(size_t)(r + 8) * G4 + c0 + 1];
                }
                float p00 = __shfl_xor_sync(0xffffffffu, v00, 1);
                float p01 = __shfl_xor_sync(0xffffffffu, v01, 1);
                float p10 = __shfl_xor_sync(0xffffffffu, v10, 1);
                float p11 = __shfl_xor_sync(0xffffffffu, v11, 1);
                if ((tg & 1) == 0) {
                    const int n = c0 >> 2;
                    {
                        float cold = cstate[(size_t)r * Asz + n];
                        float c2 = sigf(v01) * cold + sigf(v00) * tanhf_fast(p00);
                        cstate[(size_t)r * Asz + n] = c2;
                        hout[(size_t)r * Asz + n] = __float2bfloat16_rn(sigf(p01) * tanhf_fast(c2));
                    }
                    {
                        float cold = cstate[(size_t)(r + 8) * Asz + n];
                        float c2 = sigf(v11) * cold + sigf(v10) * tanhf_fast(p10);
                        cstate[(size_t)(r + 8) * Asz + n] = c2;
                        hout[(size_t)(r + 8) * Asz + n] = __float2bfloat16_rn(sigf(p11) * tanhf_fast(c2));
                    }
                }
            }
        }
    }
}

// ---------------------------------------------------------------------------
// Head phase: 64x48 tile, all 128 CTAs. Warp tile 32x8 (12 warps: 2M x 6N).
// pred = sigmoid(h2 @ Wl^T + bl) -> prevb (bf16) + out (fp32)
// ---------------------------------------------------------------------------
__device__ __forceinline__ void phase_head(
    uint32_t sb, int tid, int m0, int n0,
    const bf16* __restrict__ X,
    const float* __restrict__ biasv,
    bf16* __restrict__ prevb, float* __restrict__ outp)
{
    const int warp = tid >> 5;
    const int lane = tid & 31;
    const int wmi  = warp / 6;           // 0..1 (M, 32 rows)
    const int wni  = warp % 6;           // 0..5 (N, 8 cols)
    const int g    = lane >> 2;
    const int tg   = lane & 3;
    const int mi   = lane >> 3;
    const int lr   = lane & 7;
    const int lh   = (lane >> 3) & 1;

    float acc[2][4];
    #pragma unroll
    for (int ms = 0; ms < 2; ms++)
        #pragma unroll
        for (int r = 0; r < 4; r++) acc[ms][r] = 0.0f;

    auto fill = [&](int c) {
        const uint32_t sA = sb + (c % NSTG) * STGH;
        const uint32_t sW = sA + HTM * ROWB;
        #pragma unroll
        for (int i = 0; i < 2; i++) {          // A: 64 rows x 8 segs = 512
            int f = tid + i * NT;
            if (f < HTM * 8) {
                int row = f >> 3, seg = f & 7;
                cpa16(sA + row * ROWB + seg * 16,
                      X + (size_t)(m0 + row) * Asz + c * KC + seg * 8);
            }
        }
        {                                       // W: 48 rows x 8 segs = 384 = NT
            int row = tid >> 3, seg = tid & 7;
            cpa16(sW + row * ROWB + seg * 16,
                  ((const bf16*)g_Wlb) + (size_t)(n0 + row) * Asz + c * KC + seg * 8);
        }
        CP_COMMIT();
    };

    auto compute = [&](int buf) {
        const uint32_t sA = sb + buf * STGH;
        const uint32_t sW = sA + HTM * ROWB;
        const uint32_t aB = sA + (wmi * 32 + (mi & 1) * 8 + lr) * ROWB + (mi >> 1) * 16;
        const uint32_t wB = sW + (wni * 8 + lr) * ROWB + lh * 16;
        #pragma unroll
        for (int kt = 0; kt < 4; kt++) {
            uint32_t a0[4], a1[4], b[2];
            ldsm_x4(a0, aB + kt * 32);
            ldsm_x4(a1, aB + 16 * ROWB + kt * 32);
            ldsm_x2(b, wB + kt * 32);
            mma_bf16(acc[0], a0, b[0], b[1]);
            mma_bf16(acc[1], a1, b[0], b[1]);
        }
    };

    fill(0); fill(1);
    const int nc = Asz / KC;   // 6
    for (int c = 0; c < nc; c++) {
        if (c + 1 < nc) cp_wait<1>(); else cp_wait<0>();
        __syncthreads();
        if (c + 2 < nc) fill(c + 2);
        compute(c % NSTG);
    }

    #pragma unroll
    for (int ms = 0; ms < 2; ms++) {
        const int r  = m0 + wmi * 32 + ms * 16 + g;
        const int c0 = n0 + wni * 8 + 2 * tg;
        float v00 = sigf(acc[ms][0] + biasv[c0]);
        float v01 = sigf(acc[ms][1] + biasv[c0 + 1]);
        float v10 = sigf(acc[ms][2] + biasv[c0]);
        float v11 = sigf(acc[ms][3] + biasv[c0 + 1]);
        prevb[(size_t)r * Asz + c0]           = __float2bfloat16_rn(v00);
        prevb[(size_t)r * Asz + c0 + 1]       = __float2bfloat16_rn(v01);
        prevb[(size_t)(r + 8) * Asz + c0]     = __float2bfloat16_rn(v10);
        prevb[(size_t)(r + 8) * Asz + c0 + 1] = __float2bfloat16_rn(v11);
        outp[(size_t)r * OUTLD + c0]           = v00;
        outp[(size_t)r * OUTLD + c0 + 1]       = v01;
        outp[(size_t)(r + 8) * OUTLD + c0]     = v10;
        outp[(size_t)(r + 8) * OUTLD + c0 + 1] = v11;
    }
}

// ---------------------------------------------------------------------------
// tagbias kernel (standalone MODE0, grid (16,8))
// ---------------------------------------------------------------------------
__global__ void __launch_bounds__(NT) tag_kernel()
{
    extern __shared__ __align__(128) unsigned char dsm[];
    const uint32_t sb = smem_u32(dsm);
    phase_gemm<0>(sb, threadIdx.x, blockIdx.y * TM, blockIdx.x * TN,
                  (const bf16*)g_tagsb, Tsz, Tsz / KC, 0,
                  nullptr, (const bf16*)g_Wtag, Tsz, 0,
                  g_biasI[0], nullptr,
                  g_tagbias, nullptr, nullptr, true);
}

// ---------------------------------------------------------------------------
// Persistent whole-sequence kernel (128 CTAs, single wave, bounded-spin barrier)
// ---------------------------------------------------------------------------
__global__ void __launch_bounds__(NT) seq_kernel(const float* __restrict__ bl,
                                                 float* __restrict__ out)
{
    extern __shared__ __align__(128) unsigned char dsm[];
    const uint32_t sb = smem_u32(dsm);
    const int tid = threadIdx.x;
    const int bx  = blockIdx.x;
    unsigned long long bk = 0;

    // Bounded-spin grid barrier. Worst case per barrier ~64 ms (1M polls);
    // 196 barriers -> <=13 s/launch even on total logic failure, so the
    // container can never time out; a bug degrades to a fast wrong answer.
    auto gbar = [&]() {
        __syncthreads();
        if (tid == 0) {
            __threadfence();
            atomicAdd(&g_cnt, 1ULL);
            const unsigned long long target = (unsigned long long)NCTA * bk;
            int guard = 0;
            while (*(volatile unsigned long long*)&g_cnt < target) {
                __nanosleep(32);
                if (++guard > 1000000) break;
            }
            __threadfence();
        }
        __syncthreads();
    };

    // prefill chunks 0,1 (the H-half of the next layer phase)
    auto prefill2 = [&](const bf16* H, const bf16* W, int n0, int m0) {
        fill_chunk(sb, tid, 0, H, Asz, 0,  W, 768, Asz,      n0, m0);
        fill_chunk(sb, tid, 1, H, Asz, KC, W, 768, Asz + KC, n0, m0);
    };

    const int n0F = (bx & 15) * TN;      // layer tile (fixed -> c ownership stable)
    const int m0F = (bx >> 4) * TM;
    const int m0H = (bx >> 3) * HTM;     // head tile
    const int n0H = (bx & 7) * HTN;

    // initial prefill for L0(t=1): H = h0(prv=0)
    prefill2(g_hb[0][0], (const bf16*)g_Wcomb[0], n0F, m0F);

    for (int t = 1; t < Lsz; t++) {
        const int cur = t & 1, prv = cur ^ 1;

        // layer 0
        phase_gemm<1>(sb, tid, m0F, n0F,
                      g_prevb[prv], Asz, 12, 6,
                      g_hb[0][prv], (const bf16*)g_Wcomb[0], 768, Asz,
                      nullptr, g_tagbias,
                      nullptr, g_hb[0][cur], g_c[0], false);
        prefill2(g_hb[1][prv], (const bf16*)g_Wcomb[1], n0F, m0F);
        bk++; gbar();

        // layer 1
        phase_gemm<1>(sb, tid, m0F, n0F,
                      g_hb[0][cur], Asz, 12, 6,
                      g_hb[1][prv], (const bf16*)g_Wcomb[1], 768, Asz,
                      g_biasI[1], nullptr,
                      nullptr, g_hb[1][cur], g_c[1], false);
        prefill2(g_hb[2][prv], (const bf16*)g_Wcomb[2], n0F, m0F);
        bk++; gbar();

        // layer 2 (no prefill: head's X not published yet)
        phase_gemm<1>(sb, tid, m0F, n0F,
                      g_hb[1][cur], Asz, 12, 6,
                      g_hb[2][prv], (const bf16*)g_Wcomb[2], 768, Asz,
                      g_biasI[2], nullptr,
                      nullptr, g_hb[2][cur], g_c[2], false);
        bk++; gbar();

        // head (ALL 128 CTAs, 64x48 tiles)
        phase_head(sb, tid, m0H, n0H,
                   g_hb[2][cur], bl,
                   g_prevb[cur], out + (size_t)t * Asz);
        __syncthreads();   // head smem layout overlaps layer prefill buffers
        if (t + 1 < Lsz)   // prefill L0(t+1): H = h0(t) (published 3 barriers ago)
            prefill2(g_hb[0][cur], (const bf16*)g_Wcomb[0], n0F, m0F);
        bk++; gbar();
    }
}

// ---------------------------------------------------------------------------
// Launch sequence (graph-capturable: 4 kernel nodes)
// ---------------------------------------------------------------------------
extern "C" void kernel_launch(void* const* d_in, const int* in_sizes, int n_in,
                              void* d_out, int out_size)
{
    const float* tags = (const float*)d_in[2];
    const float* Wih0 = (const float*)d_in[4];
    const float* Whh0 = (const float*)d_in[5];
    const float* bih0 = (const float*)d_in[6];
    const float* bhh0 = (const float*)d_in[7];
    const float* Wih1 = (const float*)d_in[8];
    const float* Whh1 = (const float*)d_in[9];
    const float* bih1 = (const float*)d_in[10];
    const float* bhh1 = (const float*)d_in[11];
    const float* Wih2 = (const float*)d_in[12];
    const float* Whh2 = (const float*)d_in[13];
    const float* bih2 = (const float*)d_in[14];
    const float* bhh2 = (const float*)d_in[15];
    const float* Wl   = (const float*)d_in[16];
    const float* bl   = (const float*)d_in[17];
    float* out = (float*)d_out;

    cudaFuncSetAttribute(tag_kernel, cudaFuncAttributeMaxDynamicSharedMemorySize, SMEMB);
    cudaFuncSetAttribute(seq_kernel, cudaFuncAttributeMaxDynamicSharedMemorySize, SMEMB);

    // 1) reset barrier counter
    reset_kernel<<<1, 1>>>();

    // 2) prep: conversions + init
    prep_kernel<<<1024, 256>>>(tags, Wih0, Whh0, bih0, bhh0,
                               Wih1, Whh1, bih1, bhh1,
                               Wih2, Whh2, bih2, bhh2, Wl, out);

    // 3) tagbias = tags @ Wtag^T + biasI[0]
    tag_kernel<<<dim3(G4 / TN, Bsz / TM), NT, SMEMB>>>();

    // 4) persistent sequence
    seq_kernel<<<NCTA, NT, SMEMB>>>(bl, out);
}